// round 1
// baseline (speedup 1.0000x reference)
#include <cuda_runtime.h>
#include <math.h>

#define Bn   16
#define Cc   512
#define Lh   1024
#define Gg   8
#define CPG  64      // channels per group
#define NH   4
#define HD   128
#define EPSv 1e-5f

// ---------------- scratch (device globals: allocation-guard safe) ----------
__device__ float g_xn[Bn * Cc * Lh];        // groupnorm output      (32 MB)
__device__ float g_qkv[Bn * 3 * Cc * Lh];   // qkv activations       (96 MB)
__device__ float g_attno[Bn * Cc * Lh];     // attention output      (32 MB)
__device__ float g_mean[Bn * Gg];
__device__ float g_rstd[Bn * Gg];

// ---------------- GroupNorm: stats --------------------------------------
// one block per (b, g); group block is contiguous: CPG*Lh = 65536 floats
__global__ __launch_bounds__(256) void gn_stats(const float* __restrict__ x)
{
    int bg = blockIdx.x;
    const float4* p = (const float4*)(x + (size_t)bg * CPG * Lh);
    float s = 0.f, sq = 0.f;
    for (int i = threadIdx.x; i < CPG * Lh / 4; i += 256) {
        float4 v = p[i];
        s  += v.x + v.y + v.z + v.w;
        sq += v.x * v.x + v.y * v.y + v.z * v.z + v.w * v.w;
    }
    __shared__ float ss[256], ssq[256];
    ss[threadIdx.x] = s; ssq[threadIdx.x] = sq;
    __syncthreads();
    for (int st = 128; st > 0; st >>= 1) {
        if (threadIdx.x < st) {
            ss[threadIdx.x]  += ss[threadIdx.x + st];
            ssq[threadIdx.x] += ssq[threadIdx.x + st];
        }
        __syncthreads();
    }
    if (threadIdx.x == 0) {
        const float inv_n = 1.0f / (CPG * Lh);
        float mean = ss[0] * inv_n;
        float var  = ssq[0] * inv_n - mean * mean;
        g_mean[bg] = mean;
        g_rstd[bg] = rsqrtf(var + EPSv);
    }
}

// ---------------- GroupNorm: apply --------------------------------------
__global__ __launch_bounds__(256) void gn_apply(const float* __restrict__ x,
                                                const float* __restrict__ gamma,
                                                const float* __restrict__ beta)
{
    int idx = blockIdx.x * 256 + threadIdx.x;      // float4 index
    int e   = idx * 4;
    int c   = (e / Lh) % Cc;
    int bg  = e / (CPG * Lh);                       // = b*Gg + c/CPG
    float rstd = g_rstd[bg];
    float ga   = gamma[c] * rstd;
    float be   = beta[c] - g_mean[bg] * ga;
    float4 v = ((const float4*)x)[idx];
    float4 o;
    o.x = v.x * ga + be;  o.y = v.y * ga + be;
    o.z = v.z * ga + be;  o.w = v.w * ga + be;
    ((float4*)g_xn)[idx] = o;
}

// ---------------- SGEMM: C[b] = A @ Bmat[b] + bias (+ resid) -------------
// A: [M,K] row-major (shared weight). Bmat: per-batch [K, Lh]. N fixed = Lh.
// 64x64 tile, BK=16, 256 threads, 4x4 per thread.
__global__ __launch_bounds__(256) void sgemm64(const float* __restrict__ A,
                                               const float* __restrict__ Bmat,
                                               float* __restrict__ Cmat,
                                               const float* __restrict__ bias,
                                               const float* __restrict__ resid,
                                               int M, int K)
{
    const int bnc = blockIdx.x * 64;
    const int bmc = blockIdx.y * 64;
    const int b   = blockIdx.z;
    const float* Bp = Bmat + (size_t)b * K * Lh;
    float*       Cp = Cmat + (size_t)b * M * Lh;
    const float* Rp = resid ? resid + (size_t)b * M * Lh : nullptr;

    __shared__ float As[16][68];
    __shared__ float Bs[16][68];

    const int tid = threadIdx.x;
    const int tr  = tid / 16;          // 0..15 -> C rows tr*4..+4
    const int tc  = tid % 16;          // 0..15 -> C cols tc*4..+4

    const int am = tid / 4;            // 0..63
    const int ak = (tid % 4) * 4;      // 0,4,8,12
    const int bk = tid / 16;           // 0..15
    const int bn4 = (tid % 16) * 4;    // 0..60

    float acc[4][4] = {};

    for (int k0 = 0; k0 < K; k0 += 16) {
        float4 av = *(const float4*)&A[(size_t)(bmc + am) * K + k0 + ak];
        float4 bv = *(const float4*)&Bp[(size_t)(k0 + bk) * Lh + bnc + bn4];
        As[ak + 0][am] = av.x; As[ak + 1][am] = av.y;
        As[ak + 2][am] = av.z; As[ak + 3][am] = av.w;
        *(float4*)&Bs[bk][bn4] = bv;
        __syncthreads();
#pragma unroll
        for (int kk = 0; kk < 16; kk++) {
            float4 a  = *(const float4*)&As[kk][tr * 4];
            float4 bb = *(const float4*)&Bs[kk][tc * 4];
            acc[0][0] += a.x * bb.x; acc[0][1] += a.x * bb.y;
            acc[0][2] += a.x * bb.z; acc[0][3] += a.x * bb.w;
            acc[1][0] += a.y * bb.x; acc[1][1] += a.y * bb.y;
            acc[1][2] += a.y * bb.z; acc[1][3] += a.y * bb.w;
            acc[2][0] += a.z * bb.x; acc[2][1] += a.z * bb.y;
            acc[2][2] += a.z * bb.z; acc[2][3] += a.z * bb.w;
            acc[3][0] += a.w * bb.x; acc[3][1] += a.w * bb.y;
            acc[3][2] += a.w * bb.z; acc[3][3] += a.w * bb.w;
        }
        __syncthreads();
    }

#pragma unroll
    for (int i = 0; i < 4; i++) {
        int row = bmc + tr * 4 + i;
        float bi = bias[row];
        size_t off = (size_t)row * Lh + bnc + tc * 4;
        float4 o;
        o.x = acc[i][0] + bi; o.y = acc[i][1] + bi;
        o.z = acc[i][2] + bi; o.w = acc[i][3] + bi;
        if (Rp) {
            float4 r = *(const float4*)&Rp[off];
            o.x += r.x; o.y += r.y; o.z += r.z; o.w += r.w;
        }
        *(float4*)&Cp[off] = o;
    }
}

// ---------------- Flash attention ---------------------------------------
// grid: (16 q-tiles, NH, Bn); 256 threads; 64-query x 64-key tiles, hd=128.
// Dynamic smem layout (floats):
//   Qs [128][64]  at 0      (q[d][r])
//   Ks [128][64]  at 8192   (k[d][m])
//   Vs [64][132]  at 16384  (v[m][d], padded)
//   Ps [64][68]   at 24832  (probs, padded)
#define SMEM_FLOATS 29184   // 116736 bytes

__global__ __launch_bounds__(256) void flash_attn()
{
    extern __shared__ float sm[];
    float* Qs = sm;
    float* Ks = sm + 8192;
    float* Vs = sm + 16384;
    float* Ps = sm + 24832;

    const int qt = blockIdx.x;
    const int h  = blockIdx.y;
    const int b  = blockIdx.z;
    const float* q = g_qkv + ((size_t)b * 3 * Cc + h * HD) * Lh;
    const float* k = q + (size_t)Cc * Lh;
    const float* v = k + (size_t)Cc * Lh;
    float*       o = g_attno + ((size_t)b * Cc + h * HD) * Lh;
    const int l0 = qt * 64;

    const int tid = threadIdx.x;
    const int tr  = tid / 16;            // row group (4 rows)
    const int tc  = tid % 16;

    const int rr = (tid % 16) * 4;       // loader: 4 cols
    const int dd = tid / 16;             // loader: row within pass

    // load Q tile (stays resident all iterations)
#pragma unroll
    for (int p = 0; p < 8; p++) {
        int d = dd + p * 16;
        *(float4*)&Qs[d * 64 + rr] = *(const float4*)&q[(size_t)d * Lh + l0 + rr];
    }

    float mi[4], li[4], O[4][8];
#pragma unroll
    for (int i = 0; i < 4; i++) {
        mi[i] = -1e30f; li[i] = 0.f;
#pragma unroll
        for (int j = 0; j < 8; j++) O[i][j] = 0.f;
    }
    const float scale = 0.08838834764831845f;   // 1/sqrt(128)

    for (int mt = 0; mt < 16; mt++) {
        const int m0 = mt * 64;
        __syncthreads();                        // prev-iter readers done
        // load K tile: Ks[d][m]
#pragma unroll
        for (int p = 0; p < 8; p++) {
            int d = dd + p * 16;
            *(float4*)&Ks[d * 64 + rr] = *(const float4*)&k[(size_t)d * Lh + m0 + rr];
        }
        // load V tile transposed: Vs[m][d]
#pragma unroll
        for (int p = 0; p < 8; p++) {
            int d = dd + p * 16;
            float4 vv = *(const float4*)&v[(size_t)d * Lh + m0 + rr];
            Vs[(rr + 0) * 132 + d] = vv.x;
            Vs[(rr + 1) * 132 + d] = vv.y;
            Vs[(rr + 2) * 132 + d] = vv.z;
            Vs[(rr + 3) * 132 + d] = vv.w;
        }
        __syncthreads();

        // S = Q^T K  (4x4 per thread)
        float s[4][4] = {};
#pragma unroll 4
        for (int d = 0; d < 128; d++) {
            float4 a  = *(const float4*)&Qs[d * 64 + tr * 4];
            float4 bb = *(const float4*)&Ks[d * 64 + tc * 4];
            s[0][0] += a.x * bb.x; s[0][1] += a.x * bb.y;
            s[0][2] += a.x * bb.z; s[0][3] += a.x * bb.w;
            s[1][0] += a.y * bb.x; s[1][1] += a.y * bb.y;
            s[1][2] += a.y * bb.z; s[1][3] += a.y * bb.w;
            s[2][0] += a.z * bb.x; s[2][1] += a.z * bb.y;
            s[2][2] += a.z * bb.z; s[2][3] += a.z * bb.w;
            s[3][0] += a.w * bb.x; s[3][1] += a.w * bb.y;
            s[3][2] += a.w * bb.z; s[3][3] += a.w * bb.w;
        }

        // online softmax per row (rows shared by 16 lanes with same tr)
#pragma unroll
        for (int i = 0; i < 4; i++) {
#pragma unroll
            for (int j = 0; j < 4; j++) s[i][j] *= scale;
            float mx = fmaxf(fmaxf(s[i][0], s[i][1]), fmaxf(s[i][2], s[i][3]));
#pragma unroll
            for (int off = 8; off >= 1; off >>= 1)
                mx = fmaxf(mx, __shfl_xor_sync(0xffffffffu, mx, off));
            float mnew  = fmaxf(mi[i], mx);
            float alpha = __expf(mi[i] - mnew);
            float psum = 0.f;
#pragma unroll
            for (int j = 0; j < 4; j++) {
                float pv = __expf(s[i][j] - mnew);
                Ps[(tr * 4 + i) * 68 + tc * 4 + j] = pv;
                psum += pv;
            }
#pragma unroll
            for (int off = 8; off >= 1; off >>= 1)
                psum += __shfl_xor_sync(0xffffffffu, psum, off);
            li[i] = li[i] * alpha + psum;
            mi[i] = mnew;
#pragma unroll
            for (int j = 0; j < 8; j++) O[i][j] *= alpha;
        }
        __syncwarp();   // Ps rows are produced+consumed within one warp

        // O += P @ V   (thread owns rows tr*4..+4, dims tc*8..+8)
#pragma unroll 4
        for (int m = 0; m < 64; m++) {
            float p0 = Ps[(tr * 4 + 0) * 68 + m];
            float p1 = Ps[(tr * 4 + 1) * 68 + m];
            float p2 = Ps[(tr * 4 + 2) * 68 + m];
            float p3 = Ps[(tr * 4 + 3) * 68 + m];
            float4 va = *(const float4*)&Vs[m * 132 + tc * 8];
            float4 vb = *(const float4*)&Vs[m * 132 + tc * 8 + 4];
            O[0][0] += p0 * va.x; O[0][1] += p0 * va.y; O[0][2] += p0 * va.z; O[0][3] += p0 * va.w;
            O[0][4] += p0 * vb.x; O[0][5] += p0 * vb.y; O[0][6] += p0 * vb.z; O[0][7] += p0 * vb.w;
            O[1][0] += p1 * va.x; O[1][1] += p1 * va.y; O[1][2] += p1 * va.z; O[1][3] += p1 * va.w;
            O[1][4] += p1 * vb.x; O[1][5] += p1 * vb.y; O[1][6] += p1 * vb.z; O[1][7] += p1 * vb.w;
            O[2][0] += p2 * va.x; O[2][1] += p2 * va.y; O[2][2] += p2 * va.z; O[2][3] += p2 * va.w;
            O[2][4] += p2 * vb.x; O[2][5] += p2 * vb.y; O[2][6] += p2 * vb.z; O[2][7] += p2 * vb.w;
            O[3][0] += p3 * va.x; O[3][1] += p3 * va.y; O[3][2] += p3 * va.z; O[3][3] += p3 * va.w;
            O[3][4] += p3 * vb.x; O[3][5] += p3 * vb.y; O[3][6] += p3 * vb.z; O[3][7] += p3 * vb.w;
        }
    }

    // normalize and stage transposed into Qs (Qs[d][r]) for coalesced store
    __syncthreads();
#pragma unroll
    for (int i = 0; i < 4; i++) {
        float inv = 1.0f / li[i];
#pragma unroll
        for (int j = 0; j < 8; j++)
            Qs[(tc * 8 + j) * 64 + tr * 4 + i] = O[i][j] * inv;
    }
    __syncthreads();
#pragma unroll
    for (int p = 0; p < 8; p++) {
        int d = dd + p * 16;
        *(float4*)&o[(size_t)d * Lh + l0 + rr] = *(const float4*)&Qs[d * 64 + rr];
    }
}

// ---------------- launch ---------------------------------------------------
extern "C" void kernel_launch(void* const* d_in, const int* in_sizes, int n_in,
                              void* d_out, int out_size)
{
    (void)in_sizes; (void)n_in; (void)out_size;
    const float* x      = (const float*)d_in[0];
    const float* gamma  = (const float*)d_in[1];
    const float* beta   = (const float*)d_in[2];
    const float* w_qkv  = (const float*)d_in[3];
    const float* b_qkv  = (const float*)d_in[4];
    const float* w_proj = (const float*)d_in[5];
    const float* b_proj = (const float*)d_in[6];
    float* out = (float*)d_out;

    float *p_xn, *p_qkv, *p_attno;
    cudaGetSymbolAddress((void**)&p_xn, g_xn);
    cudaGetSymbolAddress((void**)&p_qkv, g_qkv);
    cudaGetSymbolAddress((void**)&p_attno, g_attno);

    cudaFuncSetAttribute(flash_attn, cudaFuncAttributeMaxDynamicSharedMemorySize,
                         SMEM_FLOATS * 4);

    gn_stats<<<Bn * Gg, 256>>>(x);
    gn_apply<<<(Bn * Cc * Lh / 4) / 256, 256>>>(x, gamma, beta);

    // QKV: M=1536, K=512
    sgemm64<<<dim3(Lh / 64, (3 * Cc) / 64, Bn), 256>>>(w_qkv, p_xn, p_qkv,
                                                       b_qkv, nullptr, 3 * Cc, Cc);
    // attention
    flash_attn<<<dim3(Lh / 64, NH, Bn), 256, SMEM_FLOATS * 4>>>();

    // proj + bias + residual: M=512, K=512
    sgemm64<<<dim3(Lh / 64, Cc / 64, Bn), 256>>>(w_proj, p_attno, out,
                                                 b_proj, x, Cc, Cc);
}

// round 3
// speedup vs baseline: 3.5082x; 3.5082x over previous
#include <cuda_runtime.h>
#include <math.h>
#include <stdint.h>

#define Bn   16
#define Cc   512
#define Lh   1024
#define Gg   8
#define CPG  64
#define NH   4
#define HD   128
#define EPSv 1e-5f

// ---------------- scratch ---------------------------------------------------
__device__ float g_xnT[Bn * Lh * Cc];        // groupnorm out, [b][l][c] tf32
__device__ float g_qkv[Bn * 3 * Cc * Lh];    // qkv, [b][3c][l] fp32
__device__ float g_attnoT[Bn * Lh * Cc];     // attn out, [b][l][c] tf32
__device__ float g_wqkvT[3 * Cc * Cc];       // tf32 weights
__device__ float g_wprojT[Cc * Cc];
__device__ float g_mean[Bn * Gg];
__device__ float g_rstd[Bn * Gg];

// ---------------- helpers ---------------------------------------------------
__device__ __forceinline__ uint32_t smem_u32(const void* p) {
    uint32_t a;
    asm("{ .reg .u64 t; cvta.to.shared.u64 t, %1; cvt.u32.u64 %0, t; }"
        : "=r"(a) : "l"(p));
    return a;
}
__device__ __forceinline__ void cp16(uint32_t s, const float* g) {
    asm volatile("cp.async.cg.shared.global [%0], [%1], 16;" :: "r"(s), "l"(g));
}
#define CP_COMMIT() asm volatile("cp.async.commit_group;" ::: "memory")
#define CP_WAIT1()  asm volatile("cp.async.wait_group 1;" ::: "memory")

__device__ __forceinline__ float cvt_tf32(float x) {
    uint32_t o;
    asm("cvt.rna.tf32.f32 %0, %1;" : "=r"(o) : "f"(x));
    return __uint_as_float(o);
}
// D += A(16x8,row) * B(8x8,col)  tf32
__device__ __forceinline__ void mma_tf32(float* d, const uint32_t* a,
                                         uint32_t b0, uint32_t b1) {
    asm volatile(
        "mma.sync.aligned.m16n8k8.row.col.f32.tf32.tf32.f32 "
        "{%0,%1,%2,%3}, {%4,%5,%6,%7}, {%8,%9}, {%0,%1,%2,%3};"
        : "+f"(d[0]), "+f"(d[1]), "+f"(d[2]), "+f"(d[3])
        : "r"(a[0]), "r"(a[1]), "r"(a[2]), "r"(a[3]), "r"(b0), "r"(b1));
}

// ---------------- weight cvt -------------------------------------------------
__global__ __launch_bounds__(256) void cvt_w(const float* __restrict__ w,
                                             float* __restrict__ o, int n)
{
    int i = blockIdx.x * 256 + threadIdx.x;
    if (i < n) o[i] = cvt_tf32(w[i]);
}

// ---------------- GroupNorm: stats ------------------------------------------
__global__ __launch_bounds__(256) void gn_stats(const float* __restrict__ x)
{
    int bg = blockIdx.x;
    const float4* p = (const float4*)(x + (size_t)bg * CPG * Lh);
    float s = 0.f, sq = 0.f;
    for (int i = threadIdx.x; i < CPG * Lh / 4; i += 256) {
        float4 v = p[i];
        s  += v.x + v.y + v.z + v.w;
        sq += v.x * v.x + v.y * v.y + v.z * v.z + v.w * v.w;
    }
    __shared__ float ss[256], ssq[256];
    ss[threadIdx.x] = s; ssq[threadIdx.x] = sq;
    __syncthreads();
    for (int st = 128; st > 0; st >>= 1) {
        if (threadIdx.x < st) {
            ss[threadIdx.x]  += ss[threadIdx.x + st];
            ssq[threadIdx.x] += ssq[threadIdx.x + st];
        }
        __syncthreads();
    }
    if (threadIdx.x == 0) {
        const float inv_n = 1.0f / (CPG * Lh);
        float mean = ss[0] * inv_n;
        float var  = ssq[0] * inv_n - mean * mean;
        g_mean[bg] = mean;
        g_rstd[bg] = rsqrtf(var + EPSv);
    }
}

// ---------------- GroupNorm: apply + transpose to [l, c], tf32 --------------
__global__ __launch_bounds__(256) void gn_apply_t(const float* __restrict__ x,
                                                  const float* __restrict__ gamma,
                                                  const float* __restrict__ beta)
{
    __shared__ float t[32][33];
    int bb = blockIdx.z;
    int c0 = blockIdx.y * 32;
    int l0 = blockIdx.x * 32;
    int tx = threadIdx.x & 31, ty = threadIdx.x >> 5;
    const float* xp = x + (size_t)bb * Cc * Lh;
#pragma unroll
    for (int i = 0; i < 4; i++) {
        int c = c0 + ty + i * 8;
        int bg = bb * Gg + c / CPG;
        float rstd = g_rstd[bg];
        float ga   = gamma[c] * rstd;
        float be   = beta[c] - g_mean[bg] * ga;
        t[ty + i * 8][tx] = xp[(size_t)c * Lh + l0 + tx] * ga + be;
    }
    __syncthreads();
    float* o = g_xnT + (size_t)bb * Lh * Cc;
#pragma unroll
    for (int i = 0; i < 4; i++) {
        int l = l0 + ty + i * 8;
        o[(size_t)l * Cc + c0 + tx] = cvt_tf32(t[tx][ty + i * 8]);
    }
}

// ---------------- tf32 mma GEMM ---------------------------------------------
// C[b][M][1024] = A[M,512] @ Bact[b][1024,512]^T  (+bias, +resid)
// block 128x128, 8 warps (2x4), warp 64x32; BK=32, 3-stage cp.async
#define GSTAGE_FL 9216           // As 128x36 + Bs 128x36
#define GSMEM_B   (3 * GSTAGE_FL * 4)

__device__ __forceinline__ void gemm_load(uint32_t sbase, int stage,
                                          const float* Ap, const float* Bp,
                                          int kc, int tid)
{
    uint32_t as = sbase + stage * GSTAGE_FL * 4;
    int k0 = kc * 32;
#pragma unroll
    for (int t = 0; t < 4; t++) {
        int i = tid + t * 256;
        int row = i >> 3, c4 = (i & 7) * 4;
        cp16(as + (row * 36 + c4) * 4,        Ap + (size_t)row * 512 + k0 + c4);
        cp16(as + (4608 + row * 36 + c4) * 4, Bp + (size_t)row * 512 + k0 + c4);
    }
}

__global__ __launch_bounds__(256) void sgemm_mma(const float* __restrict__ A,
                                                 const float* __restrict__ Bact,
                                                 float* __restrict__ C,
                                                 const float* __restrict__ bias,
                                                 const float* __restrict__ resid,
                                                 int M)
{
    extern __shared__ float smf[];
    const int tid  = threadIdx.x;
    const int lane = tid & 31, warp = tid >> 5;
    const int g = lane >> 2, t4 = lane & 3;
    const int wm = (warp >> 2) * 64, wn = (warp & 3) * 32;
    const int bn = blockIdx.x * 128, bm = blockIdx.y * 128, b = blockIdx.z;
    const float* Ap = A + (size_t)bm * 512;
    const float* Bp = Bact + (size_t)b * Lh * 512 + (size_t)bn * 512;
    uint32_t sbase = smem_u32(smf);

    gemm_load(sbase, 0, Ap, Bp, 0, tid); CP_COMMIT();
    gemm_load(sbase, 1, Ap, Bp, 1, tid); CP_COMMIT();

    float acc[4][4][4];
#pragma unroll
    for (int i = 0; i < 4; i++)
#pragma unroll
        for (int j = 0; j < 4; j++)
#pragma unroll
            for (int r = 0; r < 4; r++) acc[i][j][r] = 0.f;

    for (int kc = 0; kc < 16; kc++) {
        CP_WAIT1();
        __syncthreads();
        const float* As = smf + (kc % 3) * GSTAGE_FL;
        const float* Bs = As + 4608;
#pragma unroll
        for (int ks = 0; ks < 4; ks++) {
            uint32_t a[4][4];
#pragma unroll
            for (int mf = 0; mf < 4; mf++) {
                const float* ap = As + (wm + mf * 16 + g) * 36 + ks * 8 + t4;
                a[mf][0] = __float_as_uint(ap[0]);
                a[mf][1] = __float_as_uint(ap[8 * 36]);
                a[mf][2] = __float_as_uint(ap[4]);
                a[mf][3] = __float_as_uint(ap[8 * 36 + 4]);
            }
#pragma unroll
            for (int nf = 0; nf < 4; nf++) {
                const float* bp = Bs + (wn + nf * 8 + g) * 36 + ks * 8 + t4;
                uint32_t b0 = __float_as_uint(bp[0]);
                uint32_t b1 = __float_as_uint(bp[4]);
#pragma unroll
                for (int mf = 0; mf < 4; mf++)
                    mma_tf32(acc[mf][nf], a[mf], b0, b1);
            }
        }
        if (kc + 2 < 16) gemm_load(sbase, (kc + 2) % 3, Ap, Bp, kc + 2, tid);
        CP_COMMIT();
    }

    // epilogue
#pragma unroll
    for (int mf = 0; mf < 4; mf++) {
        int r0 = bm + wm + mf * 16 + g;
        float bi0 = bias[r0], bi1 = bias[r0 + 8];
        float* C0 = C + (size_t)b * M * Lh + (size_t)r0 * Lh + bn + wn;
        float* C1 = C0 + 8 * Lh;
        const float* R0 = resid ? resid + (size_t)b * M * Lh + (size_t)r0 * Lh + bn + wn
                                : (const float*)0;
#pragma unroll
        for (int nf = 0; nf < 4; nf++) {
            int col = nf * 8 + t4 * 2;
            float2 v0 = make_float2(acc[mf][nf][0] + bi0, acc[mf][nf][1] + bi0);
            float2 v1 = make_float2(acc[mf][nf][2] + bi1, acc[mf][nf][3] + bi1);
            if (R0) {
                float2 ra = *(const float2*)&R0[col];
                float2 rb = *(const float2*)&R0[8 * Lh + col];
                v0.x += ra.x; v0.y += ra.y;
                v1.x += rb.x; v1.y += rb.y;
            }
            *(float2*)&C0[col] = v0;
            *(float2*)&C1[col] = v1;
        }
    }
}

// ---------------- flash attention (tf32 mma) --------------------------------
// block: 128 queries, 8 warps x 16 rows; K-tile 64.
// smem (floats): Qs[d128][l 136], Ks[d128][m 72], Vs[d128][m 68], Ps[l128][m 68]
#define FQ 17408
#define FK 9216
#define FV 8704
#define FP 8704
#define FSM_FL (FQ + FK + FV + FP)     // 44032 floats = 176128 B

__global__ __launch_bounds__(256) void flash_mma()
{
    extern __shared__ float sm[];
    float* Qs = sm;
    float* Ks = sm + FQ;
    float* Vs = sm + FQ + FK;
    float* Ps = sm + FQ + FK + FV;

    const int qt = blockIdx.x, h = blockIdx.y, b = blockIdx.z;
    const float* q = g_qkv + ((size_t)b * 3 * Cc + h * HD) * Lh;
    const float* k = q + (size_t)Cc * Lh;
    const float* v = k + (size_t)Cc * Lh;
    const int l0 = qt * 128;
    const int tid = threadIdx.x, lane = tid & 31, warp = tid >> 5;
    const int g = lane >> 2, t4 = lane & 3;
    const int wl = warp * 16;

    // load Q [d][l] (direct copy, contiguous stores)
#pragma unroll
    for (int t = 0; t < 16; t++) {
        int i = tid + t * 256;
        int d = i >> 5, l4 = (i & 31) * 4;
        float4 vq = *(const float4*)&q[(size_t)d * Lh + l0 + l4];
        float* dst = &Qs[d * 136 + l4];
        dst[0] = cvt_tf32(vq.x); dst[1] = cvt_tf32(vq.y);
        dst[2] = cvt_tf32(vq.z); dst[3] = cvt_tf32(vq.w);
    }

    float O[16][4];
#pragma unroll
    for (int i = 0; i < 16; i++)
#pragma unroll
        for (int j = 0; j < 4; j++) O[i][j] = 0.f;
    float mi0 = -1e30f, mi1 = -1e30f, li0 = 0.f, li1 = 0.f;
    const float scale = 0.08838834764831845f;

    for (int mt = 0; mt < 16; mt++) {
        const int m0 = mt * 64;
        __syncthreads();
#pragma unroll
        for (int t = 0; t < 8; t++) {
            int i = tid + t * 256;
            int d = i >> 4, m4 = (i & 15) * 4;
            float4 vk = *(const float4*)&k[(size_t)d * Lh + m0 + m4];
            float4 vv = *(const float4*)&v[(size_t)d * Lh + m0 + m4];
            float* dk = &Ks[d * 72 + m4];
            dk[0] = cvt_tf32(vk.x); dk[1] = cvt_tf32(vk.y);
            dk[2] = cvt_tf32(vk.z); dk[3] = cvt_tf32(vk.w);
            float* dv = &Vs[d * 68 + m4];
            dv[0] = cvt_tf32(vv.x); dv[1] = cvt_tf32(vv.y);
            dv[2] = cvt_tf32(vv.z); dv[3] = cvt_tf32(vv.w);
        }
        __syncthreads();

        // S = Q^T K : warp rows [wl, wl+16), all 64 keys
        float sacc[8][4];
#pragma unroll
        for (int i = 0; i < 8; i++)
#pragma unroll
            for (int j = 0; j < 4; j++) sacc[i][j] = 0.f;
#pragma unroll
        for (int kk = 0; kk < 16; kk++) {
            const float* qp = &Qs[(kk * 8 + t4) * 136 + wl + g];
            uint32_t a[4];
            a[0] = __float_as_uint(qp[0]);
            a[1] = __float_as_uint(qp[8]);
            a[2] = __float_as_uint(qp[4 * 136]);
            a[3] = __float_as_uint(qp[4 * 136 + 8]);
#pragma unroll
            for (int nf = 0; nf < 8; nf++) {
                const float* kp = &Ks[(kk * 8 + t4) * 72 + nf * 8 + g];
                mma_tf32(sacc[nf], a, __float_as_uint(kp[0]),
                         __float_as_uint(kp[4 * 72]));
            }
        }

        // online softmax (rows r0 = wl+g, r1 = r0+8)
        float mx0 = -1e30f, mx1 = -1e30f;
#pragma unroll
        for (int nf = 0; nf < 8; nf++) {
            sacc[nf][0] *= scale; sacc[nf][1] *= scale;
            sacc[nf][2] *= scale; sacc[nf][3] *= scale;
            mx0 = fmaxf(mx0, fmaxf(sacc[nf][0], sacc[nf][1]));
            mx1 = fmaxf(mx1, fmaxf(sacc[nf][2], sacc[nf][3]));
        }
        mx0 = fmaxf(mx0, __shfl_xor_sync(0xffffffffu, mx0, 1));
        mx0 = fmaxf(mx0, __shfl_xor_sync(0xffffffffu, mx0, 2));
        mx1 = fmaxf(mx1, __shfl_xor_sync(0xffffffffu, mx1, 1));
        mx1 = fmaxf(mx1, __shfl_xor_sync(0xffffffffu, mx1, 2));
        float mn0 = fmaxf(mi0, mx0), mn1 = fmaxf(mi1, mx1);
        float al0 = __expf(mi0 - mn0), al1 = __expf(mi1 - mn1);
        mi0 = mn0; mi1 = mn1;
        float ps0 = 0.f, ps1 = 0.f;
        float* P0 = &Ps[(wl + g) * 68 + 2 * t4];
        float* P1 = P0 + 8 * 68;
#pragma unroll
        for (int nf = 0; nf < 8; nf++) {
            float p00 = __expf(sacc[nf][0] - mn0);
            float p01 = __expf(sacc[nf][1] - mn0);
            float p10 = __expf(sacc[nf][2] - mn1);
            float p11 = __expf(sacc[nf][3] - mn1);
            ps0 += p00 + p01; ps1 += p10 + p11;
            *(float2*)&P0[nf * 8] = make_float2(cvt_tf32(p00), cvt_tf32(p01));
            *(float2*)&P1[nf * 8] = make_float2(cvt_tf32(p10), cvt_tf32(p11));
        }
        ps0 += __shfl_xor_sync(0xffffffffu, ps0, 1);
        ps0 += __shfl_xor_sync(0xffffffffu, ps0, 2);
        ps1 += __shfl_xor_sync(0xffffffffu, ps1, 1);
        ps1 += __shfl_xor_sync(0xffffffffu, ps1, 2);
        li0 = li0 * al0 + ps0;
        li1 = li1 * al1 + ps1;
#pragma unroll
        for (int nf = 0; nf < 16; nf++) {
            O[nf][0] *= al0; O[nf][1] *= al0;
            O[nf][2] *= al1; O[nf][3] *= al1;
        }
        __syncwarp();

        // O += P @ V
#pragma unroll
        for (int kk = 0; kk < 8; kk++) {
            const float* pp = &Ps[(wl + g) * 68 + kk * 8 + t4];
            uint32_t a[4];
            a[0] = __float_as_uint(pp[0]);
            a[1] = __float_as_uint(pp[8 * 68]);
            a[2] = __float_as_uint(pp[4]);
            a[3] = __float_as_uint(pp[8 * 68 + 4]);
#pragma unroll
            for (int nf = 0; nf < 16; nf++) {
                const float* vp = &Vs[(nf * 8 + g) * 68 + kk * 8 + t4];
                mma_tf32(O[nf], a, __float_as_uint(vp[0]),
                         __float_as_uint(vp[4]));
            }
        }
    }

    // normalize + store transposed [l][c] (tf32 for the proj GEMM)
    float inv0 = 1.0f / li0, inv1 = 1.0f / li1;
    float* oT = g_attnoT + (size_t)b * Lh * Cc + h * HD;
    int r0 = l0 + wl + g;
#pragma unroll
    for (int nf = 0; nf < 16; nf++) {
        int d = nf * 8 + 2 * t4;
        *(float2*)&oT[(size_t)r0 * Cc + d] =
            make_float2(cvt_tf32(O[nf][0] * inv0), cvt_tf32(O[nf][1] * inv0));
        *(float2*)&oT[(size_t)(r0 + 8) * Cc + d] =
            make_float2(cvt_tf32(O[nf][2] * inv1), cvt_tf32(O[nf][3] * inv1));
    }
}

// ---------------- launch ----------------------------------------------------
extern "C" void kernel_launch(void* const* d_in, const int* in_sizes, int n_in,
                              void* d_out, int out_size)
{
    (void)in_sizes; (void)n_in; (void)out_size;
    const float* x      = (const float*)d_in[0];
    const float* gamma  = (const float*)d_in[1];
    const float* beta   = (const float*)d_in[2];
    const float* w_qkv  = (const float*)d_in[3];
    const float* b_qkv  = (const float*)d_in[4];
    const float* w_proj = (const float*)d_in[5];
    const float* b_proj = (const float*)d_in[6];
    float* out = (float*)d_out;

    float *p_xnT, *p_qkv, *p_attnoT, *p_wqkvT, *p_wprojT;
    cudaGetSymbolAddress((void**)&p_xnT, g_xnT);
    cudaGetSymbolAddress((void**)&p_qkv, g_qkv);
    cudaGetSymbolAddress((void**)&p_attnoT, g_attnoT);
    cudaGetSymbolAddress((void**)&p_wqkvT, g_wqkvT);
    cudaGetSymbolAddress((void**)&p_wprojT, g_wprojT);

    cudaFuncSetAttribute(sgemm_mma, cudaFuncAttributeMaxDynamicSharedMemorySize,
                         GSMEM_B);
    cudaFuncSetAttribute(flash_mma, cudaFuncAttributeMaxDynamicSharedMemorySize,
                         FSM_FL * 4);

    cvt_w<<<(3 * Cc * Cc + 255) / 256, 256>>>(w_qkv, p_wqkvT, 3 * Cc * Cc);
    cvt_w<<<(Cc * Cc + 255) / 256, 256>>>(w_proj, p_wprojT, Cc * Cc);

    gn_stats<<<Bn * Gg, 256>>>(x);
    gn_apply_t<<<dim3(Lh / 32, Cc / 32, Bn), 256>>>(x, gamma, beta);

    // QKV: [1536,512] @ xnT[b][1024,512]^T -> g_qkv[b][1536][1024]
    sgemm_mma<<<dim3(Lh / 128, (3 * Cc) / 128, Bn), 256, GSMEM_B>>>(
        p_wqkvT, p_xnT, p_qkv, b_qkv, nullptr, 3 * Cc);

    flash_mma<<<dim3(Lh / 128, NH, Bn), 256, FSM_FL * 4>>>();

    // proj + bias + residual
    sgemm_mma<<<dim3(Lh / 128, Cc / 128, Bn), 256, GSMEM_B>>>(
        p_wprojT, p_attnoT, out, b_proj, x, Cc);
}

// round 5
// speedup vs baseline: 7.2086x; 2.0548x over previous
#include <cuda_runtime.h>
#include <cuda_bf16.h>
#include <math.h>
#include <stdint.h>

#define Bn   16
#define Cc   512
#define Lh   1024
#define Gg   8
#define CPG  64
#define NH   4
#define HD   128
#define EPSv 1e-5f

// ---------------- scratch ---------------------------------------------------
__device__ __nv_bfloat16 g_xnT[Bn * Lh * Cc];      // GN out, [b][l][c]
__device__ __nv_bfloat16 g_qkvh[Bn * 3 * Cc * Lh]; // qkv, [b][3c][l]
__device__ __nv_bfloat16 g_aoT[Bn * Lh * Cc];      // attn out, [b][l][c]
__device__ __nv_bfloat16 g_wqkvh[3 * Cc * Cc];
__device__ __nv_bfloat16 g_wprojh[Cc * Cc];
__device__ float g_mean[Bn * Gg];
__device__ float g_rstd[Bn * Gg];

// ---------------- helpers ---------------------------------------------------
__device__ __forceinline__ uint32_t smem_u32(const void* p) {
    uint32_t a;
    asm("{ .reg .u64 t; cvta.to.shared.u64 t, %1; cvt.u32.u64 %0, t; }"
        : "=r"(a) : "l"(p));
    return a;
}
__device__ __forceinline__ void cp16(uint32_t s, const void* g) {
    asm volatile("cp.async.cg.shared.global [%0], [%1], 16;" :: "r"(s), "l"(g));
}
#define CP_COMMIT() asm volatile("cp.async.commit_group;" ::: "memory")
#define CP_WAIT1()  asm volatile("cp.async.wait_group 1;" ::: "memory")
#define CP_WAIT0()  asm volatile("cp.async.wait_group 0;" ::: "memory")

__device__ __forceinline__ uint32_t packbf(float lo, float hi) {
    uint32_t d;
    asm("cvt.rn.bf16x2.f32 %0, %1, %2;" : "=r"(d) : "f"(hi), "f"(lo));
    return d;
}
__device__ __forceinline__ void mma_bf16(float* d, const uint32_t* a,
                                         uint32_t b0, uint32_t b1) {
    asm volatile(
        "mma.sync.aligned.m16n8k16.row.col.f32.bf16.bf16.f32 "
        "{%0,%1,%2,%3}, {%4,%5,%6,%7}, {%8,%9}, {%0,%1,%2,%3};"
        : "+f"(d[0]), "+f"(d[1]), "+f"(d[2]), "+f"(d[3])
        : "r"(a[0]), "r"(a[1]), "r"(a[2]), "r"(a[3]), "r"(b0), "r"(b1));
}
#define LDMX4T(r, a) \
    asm volatile("ldmatrix.sync.aligned.m8n8.x4.trans.shared.b16 " \
                 "{%0,%1,%2,%3}, [%4];" \
                 : "=r"((r)[0]), "=r"((r)[1]), "=r"((r)[2]), "=r"((r)[3]) \
                 : "r"(a))

// ---------------- weight cvt -------------------------------------------------
__global__ __launch_bounds__(256) void cvt_w(const float* __restrict__ w,
                                             __nv_bfloat16* __restrict__ o, int n)
{
    int i = blockIdx.x * 256 + threadIdx.x;
    if (i < n) o[i] = __float2bfloat16(w[i]);
}

// ---------------- GroupNorm stats -------------------------------------------
__global__ __launch_bounds__(256) void gn_stats(const float* __restrict__ x)
{
    int bg = blockIdx.x;
    const float4* p = (const float4*)(x + (size_t)bg * CPG * Lh);
    float s = 0.f, sq = 0.f;
    for (int i = threadIdx.x; i < CPG * Lh / 4; i += 256) {
        float4 v = p[i];
        s  += v.x + v.y + v.z + v.w;
        sq += v.x * v.x + v.y * v.y + v.z * v.z + v.w * v.w;
    }
    __shared__ float ss[256], ssq[256];
    ss[threadIdx.x] = s; ssq[threadIdx.x] = sq;
    __syncthreads();
    for (int st = 128; st > 0; st >>= 1) {
        if (threadIdx.x < st) {
            ss[threadIdx.x]  += ss[threadIdx.x + st];
            ssq[threadIdx.x] += ssq[threadIdx.x + st];
        }
        __syncthreads();
    }
    if (threadIdx.x == 0) {
        const float inv_n = 1.0f / (CPG * Lh);
        float mean = ss[0] * inv_n;
        float var  = ssq[0] * inv_n - mean * mean;
        g_mean[bg] = mean;
        g_rstd[bg] = rsqrtf(var + EPSv);
    }
}

// ---------------- GroupNorm apply + transpose -> bf16 [l][c] ----------------
__global__ __launch_bounds__(256) void gn_apply_t(const float* __restrict__ x,
                                                  const float* __restrict__ gamma,
                                                  const float* __restrict__ beta)
{
    __shared__ float t[32][33];
    int bb = blockIdx.z;
    int c0 = blockIdx.y * 32;
    int l0 = blockIdx.x * 32;
    int tx = threadIdx.x & 31, ty = threadIdx.x >> 5;
    const float* xp = x + (size_t)bb * Cc * Lh;
#pragma unroll
    for (int i = 0; i < 4; i++) {
        int c = c0 + ty + i * 8;
        int bg = bb * Gg + c / CPG;
        float rstd = g_rstd[bg];
        float ga   = gamma[c] * rstd;
        float be   = beta[c] - g_mean[bg] * ga;
        t[ty + i * 8][tx] = xp[(size_t)c * Lh + l0 + tx] * ga + be;
    }
    __syncthreads();
    __nv_bfloat16* o = g_xnT + (size_t)bb * Lh * Cc;
#pragma unroll
    for (int i = 0; i < 4; i++) {
        int l = l0 + ty + i * 8;
        o[(size_t)l * Cc + c0 + tx] = __float2bfloat16(t[tx][ty + i * 8]);
    }
}

// ---------------- bf16 mma GEMM ---------------------------------------------
// C[b][M][1024] = W[M,512] @ act[b][1024,512]^T  (+bias; out bf16 OR fp32+resid)
// block 128x128, 8 warps (2x4), warp 64x32; BK=32 (2 k16 steps), 3 stages
#define GST_H  10240                 // stage halfs: A 128x40 + B 128x40
#define GSMEM_B (3 * GST_H * 2)      // 61440 bytes

__device__ __forceinline__ void gemm_load(uint32_t sbase, int stage,
                                          const __nv_bfloat16* Ap,
                                          const __nv_bfloat16* Bp,
                                          int kc, int tid)
{
    uint32_t as = sbase + stage * GST_H * 2;
    int k0 = kc * 32;
#pragma unroll
    for (int t = 0; t < 2; t++) {
        int i = tid + t * 256;               // 0..511
        int row = i >> 2, c8 = (i & 3) * 8;  // 8-half segments
        cp16(as + (row * 40 + c8) * 2,            Ap + (size_t)row * 512 + k0 + c8);
        cp16(as + (5120 + row * 40 + c8) * 2,     Bp + (size_t)row * 512 + k0 + c8);
    }
}

__global__ __launch_bounds__(256) void sgemm_bf16(const __nv_bfloat16* __restrict__ A,
                                                  const __nv_bfloat16* __restrict__ Bact,
                                                  const float* __restrict__ bias,
                                                  float* __restrict__ outf,
                                                  const float* __restrict__ resid,
                                                  __nv_bfloat16* __restrict__ outh,
                                                  int M)
{
    extern __shared__ __nv_bfloat16 smh[];
    const int tid  = threadIdx.x;
    const int lane = tid & 31, warp = tid >> 5;
    const int g = lane >> 2, t4 = lane & 3;
    const int wm = (warp >> 2) * 64, wn = (warp & 3) * 32;
    const int bn = blockIdx.x * 128, bm = blockIdx.y * 128, b = blockIdx.z;
    const __nv_bfloat16* Ap = A + (size_t)bm * 512;
    const __nv_bfloat16* Bp = Bact + (size_t)b * Lh * 512 + (size_t)bn * 512;
    uint32_t sbase = smem_u32(smh);
    const uint32_t* smw = (const uint32_t*)smh;

    gemm_load(sbase, 0, Ap, Bp, 0, tid); CP_COMMIT();
    gemm_load(sbase, 1, Ap, Bp, 1, tid); CP_COMMIT();

    float acc[4][4][4];
#pragma unroll
    for (int i = 0; i < 4; i++)
#pragma unroll
        for (int j = 0; j < 4; j++)
#pragma unroll
            for (int r = 0; r < 4; r++) acc[i][j][r] = 0.f;

    for (int kc = 0; kc < 16; kc++) {
        CP_WAIT1();
        __syncthreads();
        const uint32_t* As = smw + (kc % 3) * (GST_H / 2);
        const uint32_t* Bs = As + 2560;
#pragma unroll
        for (int ks = 0; ks < 2; ks++) {
            uint32_t a[4][4];
#pragma unroll
            for (int mf = 0; mf < 4; mf++) {
                int row = wm + mf * 16 + g;
                const uint32_t* ap = As + row * 20 + ks * 8 + t4;
                a[mf][0] = ap[0];
                a[mf][1] = ap[8 * 20];
                a[mf][2] = ap[4];
                a[mf][3] = ap[8 * 20 + 4];
            }
#pragma unroll
            for (int nf = 0; nf < 4; nf++) {
                const uint32_t* bp = Bs + (wn + nf * 8 + g) * 20 + ks * 8 + t4;
                uint32_t b0 = bp[0], b1 = bp[4];
#pragma unroll
                for (int mf = 0; mf < 4; mf++)
                    mma_bf16(acc[mf][nf], a[mf], b0, b1);
            }
        }
        if (kc + 2 < 16) gemm_load(sbase, (kc + 2) % 3, Ap, Bp, kc + 2, tid);
        CP_COMMIT();
    }

    // epilogue
#pragma unroll
    for (int mf = 0; mf < 4; mf++) {
        int r0 = bm + wm + mf * 16 + g;
        float bi0 = bias[r0], bi1 = bias[r0 + 8];
        if (outh) {
            __nv_bfloat16* C0 = outh + ((size_t)b * M + r0) * Lh + bn + wn;
            __nv_bfloat16* C1 = C0 + 8 * Lh;
#pragma unroll
            for (int nf = 0; nf < 4; nf++) {
                int col = nf * 8 + t4 * 2;
                *(uint32_t*)&C0[col] = packbf(acc[mf][nf][0] + bi0,
                                              acc[mf][nf][1] + bi0);
                *(uint32_t*)&C1[col] = packbf(acc[mf][nf][2] + bi1,
                                              acc[mf][nf][3] + bi1);
            }
        } else {
            float* C0 = outf + ((size_t)b * M + r0) * Lh + bn + wn;
            float* C1 = C0 + 8 * Lh;
            const float* R0 = resid + ((size_t)b * M + r0) * Lh + bn + wn;
#pragma unroll
            for (int nf = 0; nf < 4; nf++) {
                int col = nf * 8 + t4 * 2;
                float2 ra = *(const float2*)&R0[col];
                float2 rb = *(const float2*)&R0[8 * Lh + col];
                *(float2*)&C0[col] = make_float2(acc[mf][nf][0] + bi0 + ra.x,
                                                 acc[mf][nf][1] + bi0 + ra.y);
                *(float2*)&C1[col] = make_float2(acc[mf][nf][2] + bi1 + rb.x,
                                                 acc[mf][nf][3] + bi1 + rb.y);
            }
        }
    }
}

// ---------------- flash attention (bf16 mma) --------------------------------
// block: 128 queries, 8 warps x 16 rows; key tile 64, K/V double-buffered.
// smem halfs: Qs[128d][136], Ks[2][128d][72], Vs[2][128d][72]
#define FQ_H  (128 * 136)            // 17408
#define FKV_H (128 * 72)             // 9216
#define FSM_B ((FQ_H + 4 * FKV_H) * 2)   // 108544 bytes

__global__ __launch_bounds__(256) void flash_bf16()
{
    extern __shared__ __nv_bfloat16 smh[];
    const uint32_t sb = smem_u32(smh);
    const uint32_t qb = sb;
    const uint32_t kb[2] = { sb + FQ_H * 2, sb + (FQ_H + FKV_H) * 2 };
    const uint32_t vb[2] = { sb + (FQ_H + 2 * FKV_H) * 2, sb + (FQ_H + 3 * FKV_H) * 2 };

    const int qt = blockIdx.x, h = blockIdx.y, b = blockIdx.z;
    const __nv_bfloat16* q = g_qkvh + ((size_t)b * 3 * Cc + h * HD) * Lh;
    const __nv_bfloat16* k = q + (size_t)Cc * Lh;
    const __nv_bfloat16* v = k + (size_t)Cc * Lh;
    const int l0 = qt * 128;
    const int tid = threadIdx.x, lane = tid & 31, warp = tid >> 5;
    const int g = lane >> 2, t4 = lane & 3;
    const int wl = warp * 16;
    const int j = lane & 7, b3 = (lane >> 3) & 1, b4 = (lane >> 4) & 1;

    // prologue: Q + K/V tile 0
#pragma unroll
    for (int t = 0; t < 8; t++) {
        int i = tid + t * 256;                  // 0..2047
        int row = i >> 4, seg = (i & 15) * 8;
        cp16(qb + (row * 136 + seg) * 2, q + (size_t)row * Lh + l0 + seg);
    }
#pragma unroll
    for (int t = 0; t < 4; t++) {
        int i = tid + t * 256;                  // 0..1023
        int row = i >> 3, seg = (i & 7) * 8;
        cp16(kb[0] + (row * 72 + seg) * 2, k + (size_t)row * Lh + seg);
        cp16(vb[0] + (row * 72 + seg) * 2, v + (size_t)row * Lh + seg);
    }
    CP_COMMIT();

    float O[16][4];
#pragma unroll
    for (int i = 0; i < 16; i++)
#pragma unroll
        for (int r = 0; r < 4; r++) O[i][r] = 0.f;
    float mi0 = -1e30f, mi1 = -1e30f, li0 = 0.f, li1 = 0.f;
    const float scale = 0.08838834764831845f;

    for (int mt = 0; mt < 16; mt++) {
        if (mt + 1 < 16) {
            const int m0n = (mt + 1) * 64;
            const int st = (mt + 1) & 1;
#pragma unroll
            for (int t = 0; t < 4; t++) {
                int i = tid + t * 256;
                int row = i >> 3, seg = (i & 7) * 8;
                cp16(kb[st] + (row * 72 + seg) * 2, k + (size_t)row * Lh + m0n + seg);
                cp16(vb[st] + (row * 72 + seg) * 2, v + (size_t)row * Lh + m0n + seg);
            }
            CP_COMMIT();
            CP_WAIT1();
        } else {
            CP_WAIT0();
        }
        __syncthreads();
        const int st = mt & 1;

        // S = Q^T K : rows [wl,wl+16), 64 keys
        float sacc[8][4];
#pragma unroll
        for (int i = 0; i < 8; i++)
#pragma unroll
            for (int r = 0; r < 4; r++) sacc[i][r] = 0.f;
#pragma unroll
        for (int kk = 0; kk < 8; kk++) {
            uint32_t a[4];
            LDMX4T(a, qb + ((kk * 16 + 8 * b4 + j) * 136 + wl + 8 * b3) * 2);
#pragma unroll
            for (int np = 0; np < 4; np++) {
                uint32_t bb[4];
                LDMX4T(bb, kb[st] + ((kk * 16 + 8 * b3 + j) * 72 + np * 16 + 8 * b4) * 2);
                mma_bf16(sacc[2 * np],     a, bb[0], bb[1]);
                mma_bf16(sacc[2 * np + 1], a, bb[2], bb[3]);
            }
        }

        // online softmax (rows r0=wl+g, r1=r0+8)
        float mx0 = -1e30f, mx1 = -1e30f;
#pragma unroll
        for (int nf = 0; nf < 8; nf++) {
            sacc[nf][0] *= scale; sacc[nf][1] *= scale;
            sacc[nf][2] *= scale; sacc[nf][3] *= scale;
            mx0 = fmaxf(mx0, fmaxf(sacc[nf][0], sacc[nf][1]));
            mx1 = fmaxf(mx1, fmaxf(sacc[nf][2], sacc[nf][3]));
        }
        mx0 = fmaxf(mx0, __shfl_xor_sync(0xffffffffu, mx0, 1));
        mx0 = fmaxf(mx0, __shfl_xor_sync(0xffffffffu, mx0, 2));
        mx1 = fmaxf(mx1, __shfl_xor_sync(0xffffffffu, mx1, 1));
        mx1 = fmaxf(mx1, __shfl_xor_sync(0xffffffffu, mx1, 2));
        float mn0 = fmaxf(mi0, mx0), mn1 = fmaxf(mi1, mx1);
        float al0 = __expf(mi0 - mn0), al1 = __expf(mi1 - mn1);
        mi0 = mn0; mi1 = mn1;
        float ps0 = 0.f, ps1 = 0.f;
#pragma unroll
        for (int nf = 0; nf < 8; nf++) {
            sacc[nf][0] = __expf(sacc[nf][0] - mn0);
            sacc[nf][1] = __expf(sacc[nf][1] - mn0);
            sacc[nf][2] = __expf(sacc[nf][2] - mn1);
            sacc[nf][3] = __expf(sacc[nf][3] - mn1);
            ps0 += sacc[nf][0] + sacc[nf][1];
            ps1 += sacc[nf][2] + sacc[nf][3];
        }
        ps0 += __shfl_xor_sync(0xffffffffu, ps0, 1);
        ps0 += __shfl_xor_sync(0xffffffffu, ps0, 2);
        ps1 += __shfl_xor_sync(0xffffffffu, ps1, 1);
        ps1 += __shfl_xor_sync(0xffffffffu, ps1, 2);
        li0 = li0 * al0 + ps0;
        li1 = li1 * al1 + ps1;
#pragma unroll
        for (int nd = 0; nd < 16; nd++) {
            O[nd][0] *= al0; O[nd][1] *= al0;
            O[nd][2] *= al1; O[nd][3] *= al1;
        }

        // P A-fragments straight from S C-fragments (no smem round-trip)
        uint32_t pa[4][4];
#pragma unroll
        for (int kp = 0; kp < 4; kp++) {
            pa[kp][0] = packbf(sacc[2 * kp][0],     sacc[2 * kp][1]);
            pa[kp][1] = packbf(sacc[2 * kp][2],     sacc[2 * kp][3]);
            pa[kp][2] = packbf(sacc[2 * kp + 1][0], sacc[2 * kp + 1][1]);
            pa[kp][3] = packbf(sacc[2 * kp + 1][2], sacc[2 * kp + 1][3]);
        }

        // O += P @ V   (V [d][m], direct 32b B-frag loads)
        const uint32_t* Vw = (const uint32_t*)(smh) + (vb[st] - sb) / 4;
#pragma unroll
        for (int nd = 0; nd < 16; nd++) {
            const uint32_t* vp = Vw + (nd * 8 + g) * 36;
#pragma unroll
            for (int kp = 0; kp < 4; kp++) {
                uint32_t bv0 = vp[kp * 8 + t4];
                uint32_t bv1 = vp[kp * 8 + t4 + 4];
                mma_bf16(O[nd], pa[kp], bv0, bv1);
            }
        }
        __syncthreads();
    }

    // normalize + store bf16 [l][c]
    float inv0 = 1.0f / li0, inv1 = 1.0f / li1;
    int r0 = l0 + wl + g;
    __nv_bfloat16* oT = g_aoT + ((size_t)b * Lh + r0) * Cc + h * HD;
#pragma unroll
    for (int nd = 0; nd < 16; nd++) {
        int d = nd * 8 + 2 * t4;
        *(uint32_t*)&oT[d]           = packbf(O[nd][0] * inv0, O[nd][1] * inv0);
        *(uint32_t*)&oT[8 * Cc + d]  = packbf(O[nd][2] * inv1, O[nd][3] * inv1);
    }
}

// ---------------- launch ----------------------------------------------------
extern "C" void kernel_launch(void* const* d_in, const int* in_sizes, int n_in,
                              void* d_out, int out_size)
{
    (void)in_sizes; (void)n_in; (void)out_size;
    const float* x      = (const float*)d_in[0];
    const float* gamma  = (const float*)d_in[1];
    const float* beta   = (const float*)d_in[2];
    const float* w_qkv  = (const float*)d_in[3];
    const float* b_qkv  = (const float*)d_in[4];
    const float* w_proj = (const float*)d_in[5];
    const float* b_proj = (const float*)d_in[6];
    float* out = (float*)d_out;

    __nv_bfloat16 *p_xnT, *p_qkvh, *p_aoT, *p_wqkvh, *p_wprojh;
    cudaGetSymbolAddress((void**)&p_xnT, g_xnT);
    cudaGetSymbolAddress((void**)&p_qkvh, g_qkvh);
    cudaGetSymbolAddress((void**)&p_aoT, g_aoT);
    cudaGetSymbolAddress((void**)&p_wqkvh, g_wqkvh);
    cudaGetSymbolAddress((void**)&p_wprojh, g_wprojh);

    cudaFuncSetAttribute(sgemm_bf16, cudaFuncAttributeMaxDynamicSharedMemorySize,
                         GSMEM_B);
    cudaFuncSetAttribute(flash_bf16, cudaFuncAttributeMaxDynamicSharedMemorySize,
                         FSM_B);

    cvt_w<<<(3 * Cc * Cc + 255) / 256, 256>>>(w_qkv, p_wqkvh, 3 * Cc * Cc);
    cvt_w<<<(Cc * Cc + 255) / 256, 256>>>(w_proj, p_wprojh, Cc * Cc);

    gn_stats<<<Bn * Gg, 256>>>(x);
    gn_apply_t<<<dim3(Lh / 32, Cc / 32, Bn), 256>>>(x, gamma, beta);

    // QKV: [1536,512] @ xnT[b][1024,512]^T -> bf16 g_qkvh[b][1536][1024]
    sgemm_bf16<<<dim3(Lh / 128, (3 * Cc) / 128, Bn), 256, GSMEM_B>>>(
        p_wqkvh, p_xnT, b_qkv, nullptr, nullptr, p_qkvh, 3 * Cc);

    flash_bf16<<<dim3(Lh / 128, NH, Bn), 256, FSM_B>>>();

    // proj + bias + residual -> fp32 out
    sgemm_bf16<<<dim3(Lh / 128, Cc / 128, Bn), 256, GSMEM_B>>>(
        p_wprojh, p_aoT, b_proj, out, x, nullptr, Cc);
}

// round 6
// speedup vs baseline: 7.6922x; 1.0671x over previous
#include <cuda_runtime.h>
#include <cuda_bf16.h>
#include <math.h>
#include <stdint.h>

#define Bn   16
#define Cc   512
#define Lh   1024
#define Gg   8
#define CPG  64
#define NH   4
#define HD   128
#define EPSv 1e-5f

// ---------------- scratch ---------------------------------------------------
__device__ __nv_bfloat16 g_xnT[Bn * Lh * Cc];      // GN out, [b][l][c]
__device__ __nv_bfloat16 g_qkvh[Bn * 3 * Cc * Lh]; // qkv, [b][3c][l]
__device__ __nv_bfloat16 g_aoT[Bn * Lh * Cc];      // attn out, [b][l][c]
__device__ __nv_bfloat16 g_wqkvh[3 * Cc * Cc];
__device__ __nv_bfloat16 g_wprojh[Cc * Cc];
__device__ float g_mean[Bn * Gg];
__device__ float g_rstd[Bn * Gg];

// ---------------- helpers ---------------------------------------------------
__device__ __forceinline__ uint32_t smem_u32(const void* p) {
    uint32_t a;
    asm("{ .reg .u64 t; cvta.to.shared.u64 t, %1; cvt.u32.u64 %0, t; }"
        : "=r"(a) : "l"(p));
    return a;
}
__device__ __forceinline__ void cp16(uint32_t s, const void* g) {
    asm volatile("cp.async.cg.shared.global [%0], [%1], 16;" :: "r"(s), "l"(g));
}
#define CP_COMMIT() asm volatile("cp.async.commit_group;" ::: "memory")
#define CP_WAIT1()  asm volatile("cp.async.wait_group 1;" ::: "memory")
#define CP_WAIT0()  asm volatile("cp.async.wait_group 0;" ::: "memory")

__device__ __forceinline__ uint32_t packbf(float lo, float hi) {
    uint32_t d;
    asm("cvt.rn.bf16x2.f32 %0, %1, %2;" : "=r"(d) : "f"(hi), "f"(lo));
    return d;
}
__device__ __forceinline__ float ex2f(float x) {
    float y;
    asm("ex2.approx.f32 %0, %1;" : "=f"(y) : "f"(x));
    return y;
}
__device__ __forceinline__ void mma_bf16(float* d, const uint32_t* a,
                                         uint32_t b0, uint32_t b1) {
    asm volatile(
        "mma.sync.aligned.m16n8k16.row.col.f32.bf16.bf16.f32 "
        "{%0,%1,%2,%3}, {%4,%5,%6,%7}, {%8,%9}, {%0,%1,%2,%3};"
        : "+f"(d[0]), "+f"(d[1]), "+f"(d[2]), "+f"(d[3])
        : "r"(a[0]), "r"(a[1]), "r"(a[2]), "r"(a[3]), "r"(b0), "r"(b1));
}
#define LDMX4(r, a) \
    asm volatile("ldmatrix.sync.aligned.m8n8.x4.shared.b16 " \
                 "{%0,%1,%2,%3}, [%4];" \
                 : "=r"((r)[0]), "=r"((r)[1]), "=r"((r)[2]), "=r"((r)[3]) \
                 : "r"(a))
#define LDMX4T(r, a) \
    asm volatile("ldmatrix.sync.aligned.m8n8.x4.trans.shared.b16 " \
                 "{%0,%1,%2,%3}, [%4];" \
                 : "=r"((r)[0]), "=r"((r)[1]), "=r"((r)[2]), "=r"((r)[3]) \
                 : "r"(a))

// ---------------- weight cvt -------------------------------------------------
__global__ __launch_bounds__(256) void cvt_w(const float* __restrict__ w,
                                             __nv_bfloat16* __restrict__ o, int n)
{
    int i = blockIdx.x * 256 + threadIdx.x;
    if (i < n) o[i] = __float2bfloat16(w[i]);
}

// ---------------- GroupNorm stats -------------------------------------------
__global__ __launch_bounds__(256) void gn_stats(const float* __restrict__ x)
{
    int bg = blockIdx.x;
    const float4* p = (const float4*)(x + (size_t)bg * CPG * Lh);
    float s = 0.f, sq = 0.f;
    for (int i = threadIdx.x; i < CPG * Lh / 4; i += 256) {
        float4 v = p[i];
        s  += v.x + v.y + v.z + v.w;
        sq += v.x * v.x + v.y * v.y + v.z * v.z + v.w * v.w;
    }
    __shared__ float ss[256], ssq[256];
    ss[threadIdx.x] = s; ssq[threadIdx.x] = sq;
    __syncthreads();
    for (int st = 128; st > 0; st >>= 1) {
        if (threadIdx.x < st) {
            ss[threadIdx.x]  += ss[threadIdx.x + st];
            ssq[threadIdx.x] += ssq[threadIdx.x + st];
        }
        __syncthreads();
    }
    if (threadIdx.x == 0) {
        const float inv_n = 1.0f / (CPG * Lh);
        float mean = ss[0] * inv_n;
        float var  = ssq[0] * inv_n - mean * mean;
        g_mean[bg] = mean;
        g_rstd[bg] = rsqrtf(var + EPSv);
    }
}

// ---------------- GroupNorm apply + transpose -> bf16 [l][c] ----------------
__global__ __launch_bounds__(256) void gn_apply_t(const float* __restrict__ x,
                                                  const float* __restrict__ gamma,
                                                  const float* __restrict__ beta)
{
    __shared__ float t[32][33];
    int bb = blockIdx.z;
    int c0 = blockIdx.y * 32;
    int l0 = blockIdx.x * 32;
    int tx = threadIdx.x & 31, ty = threadIdx.x >> 5;
    const float* xp = x + (size_t)bb * Cc * Lh;
#pragma unroll
    for (int i = 0; i < 4; i++) {
        int c = c0 + ty + i * 8;
        int bg = bb * Gg + c / CPG;
        float rstd = g_rstd[bg];
        float ga   = gamma[c] * rstd;
        float be   = beta[c] - g_mean[bg] * ga;
        t[ty + i * 8][tx] = xp[(size_t)c * Lh + l0 + tx] * ga + be;
    }
    __syncthreads();
    __nv_bfloat16* o = g_xnT + (size_t)bb * Lh * Cc;
    // packed bf16x2 stores: 512 (l, c-pair) items, 2 per thread
#pragma unroll
    for (int it = 0; it < 2; it++) {
        int i = threadIdx.x + it * 256;
        int l = i >> 4, cp = (i & 15) * 2;
        uint32_t v = packbf(t[cp][l], t[cp + 1][l]);
        *(uint32_t*)&o[(size_t)(l0 + l) * Cc + c0 + cp] = v;
    }
}

// ---------------- bf16 mma GEMM ---------------------------------------------
// C[b][M][1024] = W[M,512] @ act[b][1024,512]^T  (+bias; out bf16 OR fp32+resid)
// block 128x128, 8 warps (2x4), warp 64x32; BK=32 (2 k16 steps), 3 stages
#define GST_H  10240                 // stage halfs: A 128x40 + B 128x40
#define GSMEM_B (3 * GST_H * 2)      // 61440 bytes

__device__ __forceinline__ void gemm_load(uint32_t sbase, int stage,
                                          const __nv_bfloat16* Ap,
                                          const __nv_bfloat16* Bp,
                                          int kc, int tid)
{
    uint32_t as = sbase + stage * GST_H * 2;
    int k0 = kc * 32;
#pragma unroll
    for (int t = 0; t < 2; t++) {
        int i = tid + t * 256;               // 0..511
        int row = i >> 2, c8 = (i & 3) * 8;  // 8-half segments
        cp16(as + (row * 40 + c8) * 2,        Ap + (size_t)row * 512 + k0 + c8);
        cp16(as + (5120 + row * 40 + c8) * 2, Bp + (size_t)row * 512 + k0 + c8);
    }
}

__global__ __launch_bounds__(256) void sgemm_bf16(const __nv_bfloat16* __restrict__ A,
                                                  const __nv_bfloat16* __restrict__ Bact,
                                                  const float* __restrict__ bias,
                                                  float* __restrict__ outf,
                                                  const float* __restrict__ resid,
                                                  __nv_bfloat16* __restrict__ outh,
                                                  int M)
{
    extern __shared__ __nv_bfloat16 smh[];
    const int tid  = threadIdx.x;
    const int lane = tid & 31, warp = tid >> 5;
    const int g = lane >> 2, t4 = lane & 3;
    const int wm = (warp >> 2) * 64, wn = (warp & 3) * 32;
    const int bn = blockIdx.x * 128, bm = blockIdx.y * 128, b = blockIdx.z;
    const __nv_bfloat16* Ap = A + (size_t)bm * 512;
    const __nv_bfloat16* Bp = Bact + (size_t)b * Lh * 512 + (size_t)bn * 512;
    uint32_t sbase = smem_u32(smh);

    // ldmatrix lane addressing
    const int arow = (lane & 7) + ((lane & 8)  ? 8 : 0);   // m within 16
    const int acol = ((lane & 16) ? 8 : 0);                // k half-sel
    const int brow = (lane & 7) + ((lane & 16) ? 8 : 0);   // n within 16
    const int bcol = ((lane & 8)  ? 8 : 0);                // k half-sel

    gemm_load(sbase, 0, Ap, Bp, 0, tid); CP_COMMIT();
    gemm_load(sbase, 1, Ap, Bp, 1, tid); CP_COMMIT();

    float acc[4][4][4];
#pragma unroll
    for (int i = 0; i < 4; i++)
#pragma unroll
        for (int j = 0; j < 4; j++)
#pragma unroll
            for (int r = 0; r < 4; r++) acc[i][j][r] = 0.f;

    for (int kc = 0; kc < 16; kc++) {
        CP_WAIT1();
        __syncthreads();
        uint32_t abase = sbase + (kc % 3) * GST_H * 2;
        uint32_t bbase = abase + 5120 * 2;
#pragma unroll
        for (int ks = 0; ks < 2; ks++) {
            uint32_t a[4][4];
#pragma unroll
            for (int mf = 0; mf < 4; mf++)
                LDMX4(a[mf], abase +
                      ((wm + mf * 16 + arow) * 40 + ks * 16 + acol) * 2);
            uint32_t bfr[2][4];
#pragma unroll
            for (int p = 0; p < 2; p++)
                LDMX4(bfr[p], bbase +
                      ((wn + p * 16 + brow) * 40 + ks * 16 + bcol) * 2);
#pragma unroll
            for (int nf = 0; nf < 4; nf++) {
                uint32_t b0 = bfr[nf >> 1][(nf & 1) * 2];
                uint32_t b1 = bfr[nf >> 1][(nf & 1) * 2 + 1];
#pragma unroll
                for (int mf = 0; mf < 4; mf++)
                    mma_bf16(acc[mf][nf], a[mf], b0, b1);
            }
        }
        if (kc + 2 < 16) gemm_load(sbase, (kc + 2) % 3, Ap, Bp, kc + 2, tid);
        CP_COMMIT();
    }

    // epilogue
#pragma unroll
    for (int mf = 0; mf < 4; mf++) {
        int r0 = bm + wm + mf * 16 + g;
        float bi0 = bias[r0], bi1 = bias[r0 + 8];
        if (outh) {
            __nv_bfloat16* C0 = outh + ((size_t)b * M + r0) * Lh + bn + wn;
            __nv_bfloat16* C1 = C0 + 8 * Lh;
#pragma unroll
            for (int nf = 0; nf < 4; nf++) {
                int col = nf * 8 + t4 * 2;
                *(uint32_t*)&C0[col] = packbf(acc[mf][nf][0] + bi0,
                                              acc[mf][nf][1] + bi0);
                *(uint32_t*)&C1[col] = packbf(acc[mf][nf][2] + bi1,
                                              acc[mf][nf][3] + bi1);
            }
        } else {
            float* C0 = outf + ((size_t)b * M + r0) * Lh + bn + wn;
            float* C1 = C0 + 8 * Lh;
            const float* R0 = resid + ((size_t)b * M + r0) * Lh + bn + wn;
#pragma unroll
            for (int nf = 0; nf < 4; nf++) {
                int col = nf * 8 + t4 * 2;
                float2 ra = *(const float2*)&R0[col];
                float2 rb = *(const float2*)&R0[8 * Lh + col];
                *(float2*)&C0[col] = make_float2(acc[mf][nf][0] + bi0 + ra.x,
                                                 acc[mf][nf][1] + bi0 + ra.y);
                *(float2*)&C1[col] = make_float2(acc[mf][nf][2] + bi1 + rb.x,
                                                 acc[mf][nf][3] + bi1 + rb.y);
            }
        }
    }
}

// ---------------- flash attention (bf16 mma) --------------------------------
// block: 128 queries, 8 warps x 16 rows; key tile 64, K/V double-buffered.
// smem halfs: Qs[128d][136], Ks[2][128d][72], Vs[2][128d][72]
#define FQ_H  (128 * 136)            // 17408
#define FKV_H (128 * 72)             // 9216
#define FSM_B ((FQ_H + 4 * FKV_H) * 2)   // 108544 bytes

__global__ __launch_bounds__(256) void flash_bf16()
{
    extern __shared__ __nv_bfloat16 smh[];
    const uint32_t sb = smem_u32(smh);
    const uint32_t qb = sb;
    const uint32_t kb[2] = { sb + FQ_H * 2, sb + (FQ_H + FKV_H) * 2 };
    const uint32_t vb[2] = { sb + (FQ_H + 2 * FKV_H) * 2, sb + (FQ_H + 3 * FKV_H) * 2 };

    const int qt = blockIdx.x, h = blockIdx.y, b = blockIdx.z;
    const __nv_bfloat16* q = g_qkvh + ((size_t)b * 3 * Cc + h * HD) * Lh;
    const __nv_bfloat16* k = q + (size_t)Cc * Lh;
    const __nv_bfloat16* v = k + (size_t)Cc * Lh;
    const int l0 = qt * 128;
    const int tid = threadIdx.x, lane = tid & 31, warp = tid >> 5;
    const int g = lane >> 2, t4 = lane & 3;
    const int wl = warp * 16;
    const int j = lane & 7, b3 = (lane >> 3) & 1, b4 = (lane >> 4) & 1;
    // V ldmatrix addressing: rows = d, cols = m halves
    const int vdrow = ((lane >> 4) & 1) * 8 + (lane & 7);
    const int vmcol = ((lane >> 3) & 1) * 8;

    // prologue: Q + K/V tile 0
#pragma unroll
    for (int t = 0; t < 8; t++) {
        int i = tid + t * 256;                  // 0..2047
        int row = i >> 4, seg = (i & 15) * 8;
        cp16(qb + (row * 136 + seg) * 2, q + (size_t)row * Lh + l0 + seg);
    }
#pragma unroll
    for (int t = 0; t < 4; t++) {
        int i = tid + t * 256;                  // 0..1023
        int row = i >> 3, seg = (i & 7) * 8;
        cp16(kb[0] + (row * 72 + seg) * 2, k + (size_t)row * Lh + seg);
        cp16(vb[0] + (row * 72 + seg) * 2, v + (size_t)row * Lh + seg);
    }
    CP_COMMIT();

    float O[16][4];
#pragma unroll
    for (int i = 0; i < 16; i++)
#pragma unroll
        for (int r = 0; r < 4; r++) O[i][r] = 0.f;
    float mi0 = -1e30f, mi1 = -1e30f, li0 = 0.f, li1 = 0.f;
    const float sc2 = 0.08838834764831845f * 1.4426950408889634f; // scale*log2e

    for (int mt = 0; mt < 16; mt++) {
        if (mt + 1 < 16) {
            const int m0n = (mt + 1) * 64;
            const int st = (mt + 1) & 1;
#pragma unroll
            for (int t = 0; t < 4; t++) {
                int i = tid + t * 256;
                int row = i >> 3, seg = (i & 7) * 8;
                cp16(kb[st] + (row * 72 + seg) * 2, k + (size_t)row * Lh + m0n + seg);
                cp16(vb[st] + (row * 72 + seg) * 2, v + (size_t)row * Lh + m0n + seg);
            }
            CP_COMMIT();
            CP_WAIT1();
        } else {
            CP_WAIT0();
        }
        __syncthreads();
        const int st = mt & 1;

        // S = Q^T K (raw, unscaled): rows [wl,wl+16), 64 keys
        float sacc[8][4];
#pragma unroll
        for (int i = 0; i < 8; i++)
#pragma unroll
            for (int r = 0; r < 4; r++) sacc[i][r] = 0.f;
#pragma unroll
        for (int kk = 0; kk < 8; kk++) {
            uint32_t a[4];
            LDMX4T(a, qb + ((kk * 16 + 8 * b4 + j) * 136 + wl + 8 * b3) * 2);
#pragma unroll
            for (int np = 0; np < 4; np++) {
                uint32_t bb[4];
                LDMX4T(bb, kb[st] + ((kk * 16 + 8 * b3 + j) * 72 + np * 16 + 8 * b4) * 2);
                mma_bf16(sacc[2 * np],     a, bb[0], bb[1]);
                mma_bf16(sacc[2 * np + 1], a, bb[2], bb[3]);
            }
        }

        // online softmax in exp2 domain (rows r0=wl+g, r1=r0+8); mi raw
        float mx0 = -1e30f, mx1 = -1e30f;
#pragma unroll
        for (int nf = 0; nf < 8; nf++) {
            mx0 = fmaxf(mx0, fmaxf(sacc[nf][0], sacc[nf][1]));
            mx1 = fmaxf(mx1, fmaxf(sacc[nf][2], sacc[nf][3]));
        }
        mx0 = fmaxf(mx0, __shfl_xor_sync(0xffffffffu, mx0, 1));
        mx0 = fmaxf(mx0, __shfl_xor_sync(0xffffffffu, mx0, 2));
        mx1 = fmaxf(mx1, __shfl_xor_sync(0xffffffffu, mx1, 1));
        mx1 = fmaxf(mx1, __shfl_xor_sync(0xffffffffu, mx1, 2));
        float mn0 = fmaxf(mi0, mx0), mn1 = fmaxf(mi1, mx1);
        float al0 = ex2f(sc2 * (mi0 - mn0));
        float al1 = ex2f(sc2 * (mi1 - mn1));
        mi0 = mn0; mi1 = mn1;
        float c0 = sc2 * mn0, c1 = sc2 * mn1;
        float ps0 = 0.f, ps1 = 0.f;
#pragma unroll
        for (int nf = 0; nf < 8; nf++) {
            sacc[nf][0] = ex2f(fmaf(sacc[nf][0], sc2, -c0));
            sacc[nf][1] = ex2f(fmaf(sacc[nf][1], sc2, -c0));
            sacc[nf][2] = ex2f(fmaf(sacc[nf][2], sc2, -c1));
            sacc[nf][3] = ex2f(fmaf(sacc[nf][3], sc2, -c1));
            ps0 += sacc[nf][0] + sacc[nf][1];
            ps1 += sacc[nf][2] + sacc[nf][3];
        }
        ps0 += __shfl_xor_sync(0xffffffffu, ps0, 1);
        ps0 += __shfl_xor_sync(0xffffffffu, ps0, 2);
        ps1 += __shfl_xor_sync(0xffffffffu, ps1, 1);
        ps1 += __shfl_xor_sync(0xffffffffu, ps1, 2);
        li0 = li0 * al0 + ps0;
        li1 = li1 * al1 + ps1;
#pragma unroll
        for (int nd = 0; nd < 16; nd++) {
            O[nd][0] *= al0; O[nd][1] *= al0;
            O[nd][2] *= al1; O[nd][3] *= al1;
        }

        // P A-fragments straight from S C-fragments (no smem round-trip)
        uint32_t pa[4][4];
#pragma unroll
        for (int kp = 0; kp < 4; kp++) {
            pa[kp][0] = packbf(sacc[2 * kp][0],     sacc[2 * kp][1]);
            pa[kp][1] = packbf(sacc[2 * kp][2],     sacc[2 * kp][3]);
            pa[kp][2] = packbf(sacc[2 * kp + 1][0], sacc[2 * kp + 1][1]);
            pa[kp][3] = packbf(sacc[2 * kp + 1][2], sacc[2 * kp + 1][3]);
        }

        // O += P @ V  (V [d][m]; B-frags via ldmatrix.x4, 2 nd per load)
#pragma unroll
        for (int nd2 = 0; nd2 < 8; nd2++) {
#pragma unroll
            for (int kp = 0; kp < 4; kp++) {
                uint32_t bv[4];
                LDMX4(bv, vb[st] +
                      ((nd2 * 16 + vdrow) * 72 + kp * 16 + vmcol) * 2);
                mma_bf16(O[2 * nd2],     pa[kp], bv[0], bv[1]);
                mma_bf16(O[2 * nd2 + 1], pa[kp], bv[2], bv[3]);
            }
        }
        __syncthreads();
    }

    // normalize + store bf16 [l][c]
    float inv0 = 1.0f / li0, inv1 = 1.0f / li1;
    int r0 = l0 + wl + g;
    __nv_bfloat16* oT = g_aoT + ((size_t)b * Lh + r0) * Cc + h * HD;
#pragma unroll
    for (int nd = 0; nd < 16; nd++) {
        int d = nd * 8 + 2 * t4;
        *(uint32_t*)&oT[d]           = packbf(O[nd][0] * inv0, O[nd][1] * inv0);
        *(uint32_t*)&oT[8 * Cc + d]  = packbf(O[nd][2] * inv1, O[nd][3] * inv1);
    }
}

// ---------------- launch ----------------------------------------------------
extern "C" void kernel_launch(void* const* d_in, const int* in_sizes, int n_in,
                              void* d_out, int out_size)
{
    (void)in_sizes; (void)n_in; (void)out_size;
    const float* x      = (const float*)d_in[0];
    const float* gamma  = (const float*)d_in[1];
    const float* beta   = (const float*)d_in[2];
    const float* w_qkv  = (const float*)d_in[3];
    const float* b_qkv  = (const float*)d_in[4];
    const float* w_proj = (const float*)d_in[5];
    const float* b_proj = (const float*)d_in[6];
    float* out = (float*)d_out;

    __nv_bfloat16 *p_xnT, *p_qkvh, *p_aoT, *p_wqkvh, *p_wprojh;
    cudaGetSymbolAddress((void**)&p_xnT, g_xnT);
    cudaGetSymbolAddress((void**)&p_qkvh, g_qkvh);
    cudaGetSymbolAddress((void**)&p_aoT, g_aoT);
    cudaGetSymbolAddress((void**)&p_wqkvh, g_wqkvh);
    cudaGetSymbolAddress((void**)&p_wprojh, g_wprojh);

    cudaFuncSetAttribute(sgemm_bf16, cudaFuncAttributeMaxDynamicSharedMemorySize,
                         GSMEM_B);
    cudaFuncSetAttribute(flash_bf16, cudaFuncAttributeMaxDynamicSharedMemorySize,
                         FSM_B);

    cvt_w<<<(3 * Cc * Cc + 255) / 256, 256>>>(w_qkv, p_wqkvh, 3 * Cc * Cc);
    cvt_w<<<(Cc * Cc + 255) / 256, 256>>>(w_proj, p_wprojh, Cc * Cc);

    gn_stats<<<Bn * Gg, 256>>>(x);
    gn_apply_t<<<dim3(Lh / 32, Cc / 32, Bn), 256>>>(x, gamma, beta);

    // QKV: [1536,512] @ xnT[b][1024,512]^T -> bf16 g_qkvh[b][1536][1024]
    sgemm_bf16<<<dim3(Lh / 128, (3 * Cc) / 128, Bn), 256, GSMEM_B>>>(
        p_wqkvh, p_xnT, b_qkv, nullptr, nullptr, p_qkvh, 3 * Cc);

    flash_bf16<<<dim3(Lh / 128, NH, Bn), 256, FSM_B>>>();

    // proj + bias + residual -> fp32 out
    sgemm_bf16<<<dim3(Lh / 128, Cc / 128, Bn), 256, GSMEM_B>>>(
        p_wprojh, p_aoT, b_proj, out, x, nullptr, Cc);
}